// round 13
// baseline (speedup 1.0000x reference)
#include <cuda_runtime.h>
#include <cuda_bf16.h>
#include <cstdint>
#include <cstddef>

// ---------------------------------------------------------------------------
// AWD-LSTM forward: embed -> DeFINE -> 3x LSTM -> tied-embedding logits
// Shapes: B=32, T=128, V=32000, E=400, M=512, H=1152.
// Round 13: LSTM recurrence moved onto legacy tensor cores (mma.sync bf16,
// 3-term hi/lo split, gate-permuted pre-split Whh, h re-split per step in
// the epilogue). Input GEMMs (FFMA2) and logits HMMA unchanged.
// ---------------------------------------------------------------------------

#define Bb 32
#define Tt 128
#define Vv 32000
#define Ee 400
#define Mm 512
#define Hh 1152
#define NT 4096           // B*T tokens
#define LK 448            // logits K padded (400 -> 448)
#define DKE 512           // layer-2 recurrence K padded (400 -> 512)

// ---- scratch (device globals; no allocation allowed) ----
__device__ float g_PRE[NT * 4608];
__device__ float g_X0 [NT * Mm];
__device__ float g_Y0 [NT * Hh];
__device__ float g_Y1 [NT * Hh];
__device__ float g_Y2 [NT * Ee];
__device__ float g_WT [Mm * Ee];
__device__ float g_CT [Hh * 32];                     // cell state [d][32]
__device__ __nv_bfloat16 g_HB [2][2 * 32 * Hh];      // h ping-pong, hi|lo rows
__device__ __nv_bfloat16 g_WS0[(size_t)4 * Hh * Hh]; // Whh hi split (permuted)
__device__ __nv_bfloat16 g_WS1[(size_t)4 * Hh * Hh]; // Whh lo split
__device__ __nv_bfloat16 g_E0[(size_t)Vv * LK];
__device__ __nv_bfloat16 g_E1[(size_t)Vv * LK];
__device__ __nv_bfloat16 g_A0[(size_t)NT * LK];
__device__ __nv_bfloat16 g_A1[(size_t)NT * LK];

// ---- packed fp32 helpers ----
__device__ __forceinline__ unsigned long long ffma2(
    unsigned long long a, unsigned long long b, unsigned long long c)
{
    unsigned long long d;
    asm("fma.rn.f32x2 %0, %1, %2, %3;" : "=l"(d) : "l"(a), "l"(b), "l"(c));
    return d;
}
__device__ __forceinline__ unsigned long long dup2(float x)
{
    unsigned long long r;
    asm("mov.b64 %0, {%1, %1};" : "=l"(r) : "f"(x));
    return r;
}
__device__ __forceinline__ float2 unpack2(unsigned long long v)
{
    float lo, hi;
    asm("mov.b64 {%0, %1}, %2;" : "=f"(lo), "=f"(hi) : "l"(v));
    return make_float2(lo, hi);
}
union F4U { float4 f; unsigned long long u[2]; };

__device__ __forceinline__ void hmma16816(
    float& c0, float& c1, float& c2, float& c3,
    uint32_t a0, uint32_t a1, uint32_t a2, uint32_t a3,
    uint32_t b0, uint32_t b1)
{
    asm volatile(
        "mma.sync.aligned.m16n8k16.row.col.f32.bf16.bf16.f32 "
        "{%0,%1,%2,%3}, {%4,%5,%6,%7}, {%8,%9}, {%0,%1,%2,%3};"
        : "+f"(c0), "+f"(c1), "+f"(c2), "+f"(c3)
        : "r"(a0), "r"(a1), "r"(a2), "r"(a3), "r"(b0), "r"(b1));
}

// ---------------------------------------------------------------------------
// fp32 GEMM-NT (unchanged, FFMA2 inner loop)
// ---------------------------------------------------------------------------
#define GBM 128
#define GBN 128
#define GBK 8

__global__ __launch_bounds__(256) void gemm_nt(
    const float* __restrict__ A, const float* __restrict__ Bm,
    float* __restrict__ C, const float* __restrict__ bias,
    const int* __restrict__ ids, int M, int N, int K)
{
    __shared__ float As[2][GBK][GBM];
    __shared__ float Bs[2][GBK][GBN];

    const int tid = threadIdx.x;
    const int m0  = blockIdx.y * GBM;
    const int n0  = blockIdx.x * GBN;
    const int tx  = tid & 15;
    const int ty  = tid >> 4;

    const int lr = tid >> 1;
    const int kq = (tid & 1) << 2;

    const int arow = ids ? ids[m0 + lr] : (m0 + lr);
    const float* ag = A + (size_t)arow * K + kq;
    const bool bok = (n0 + lr) < N;
    const float* bg = Bm + (size_t)(bok ? (n0 + lr) : 0) * K + kq;

    unsigned long long acc2[4][8];
    #pragma unroll
    for (int p = 0; p < 4; ++p)
        #pragma unroll
        for (int j = 0; j < 8; ++j) acc2[p][j] = 0ull;

    const int nk = K / GBK;

    float4 va = *(const float4*)ag;
    float4 vb = bok ? *(const float4*)bg : make_float4(0.f, 0.f, 0.f, 0.f);

    int buf = 0;
    As[0][kq + 0][lr] = va.x; As[0][kq + 1][lr] = va.y;
    As[0][kq + 2][lr] = va.z; As[0][kq + 3][lr] = va.w;
    Bs[0][kq + 0][lr] = vb.x; Bs[0][kq + 1][lr] = vb.y;
    Bs[0][kq + 2][lr] = vb.z; Bs[0][kq + 3][lr] = vb.w;
    __syncthreads();

    for (int kt = 0; kt < nk; ++kt) {
        const bool more = (kt + 1) < nk;
        if (more) {
            va = *(const float4*)(ag + (size_t)(kt + 1) * GBK);
            if (bok) vb = *(const float4*)(bg + (size_t)(kt + 1) * GBK);
        }

        #pragma unroll
        for (int k = 0; k < GBK; ++k) {
            F4U A0u, A1u, B0u, B1u;
            A0u.f = *(const float4*)&As[buf][k][ty * 4];
            A1u.f = *(const float4*)&As[buf][k][ty * 4 + 64];
            B0u.f = *(const float4*)&Bs[buf][k][tx * 4];
            B1u.f = *(const float4*)&Bs[buf][k][tx * 4 + 64];

            const unsigned long long ap[4] = { A0u.u[0], A0u.u[1], A1u.u[0], A1u.u[1] };
            const float bvv[8] = { B0u.f.x, B0u.f.y, B0u.f.z, B0u.f.w,
                                   B1u.f.x, B1u.f.y, B1u.f.z, B1u.f.w };
            #pragma unroll
            for (int j = 0; j < 8; ++j) {
                const unsigned long long bd = dup2(bvv[j]);
                #pragma unroll
                for (int p = 0; p < 4; ++p)
                    acc2[p][j] = ffma2(ap[p], bd, acc2[p][j]);
            }
        }

        if (more) {
            const int nb = buf ^ 1;
            As[nb][kq + 0][lr] = va.x; As[nb][kq + 1][lr] = va.y;
            As[nb][kq + 2][lr] = va.z; As[nb][kq + 3][lr] = va.w;
            Bs[nb][kq + 0][lr] = vb.x; Bs[nb][kq + 1][lr] = vb.y;
            Bs[nb][kq + 2][lr] = vb.z; Bs[nb][kq + 3][lr] = vb.w;
            __syncthreads();
            buf = nb;
        }
    }

    float accf[8][8];
    #pragma unroll
    for (int p = 0; p < 4; ++p)
        #pragma unroll
        for (int j = 0; j < 8; ++j) {
            float2 tp = unpack2(acc2[p][j]);
            accf[2 * p    ][j] = tp.x;
            accf[2 * p + 1][j] = tp.y;
        }

    #pragma unroll
    for (int ih = 0; ih < 2; ++ih) {
        #pragma unroll
        for (int i = 0; i < 4; ++i) {
            const int rm = m0 + ih * 64 + ty * 4 + i;
            float* crow = C + (size_t)rm * N;
            #pragma unroll
            for (int jh = 0; jh < 2; ++jh) {
                const int cn = n0 + jh * 64 + tx * 4;
                if (cn < N) {
                    float4 bvv = make_float4(0.f, 0.f, 0.f, 0.f);
                    if (bias) bvv = *(const float4*)(bias + cn);
                    float4 o;
                    o.x = accf[ih * 4 + i][jh * 4 + 0] + bvv.x;
                    o.y = accf[ih * 4 + i][jh * 4 + 1] + bvv.y;
                    o.z = accf[ih * 4 + i][jh * 4 + 2] + bvv.z;
                    o.w = accf[ih * 4 + i][jh * 4 + 3] + bvv.w;
                    *(float4*)(crow + cn) = o;
                }
            }
        }
    }
}

// ---------------------------------------------------------------------------
// LSTM timestep on tensor cores.
// Per CTA: 32 batches x 32 gate-cols (nn = unit*4+gate, permuted W layout)
//        = 8 complete units. K = dkp (1152 or 512), chunks of 128.
// 256 threads = 4 n8-tiles x 2 k-groups; k-groups combined via smem psum.
// 3-term split: acc = a0*w0 + a0*w1 + a1*w0 (hi/lo of h and Whh).
// Epilogue: shfl_xor(1) gathers 4 gates/unit; writes y fp32, c fp32,
// h as bf16 hi/lo (operand layout for the next step).
// ---------------------------------------------------------------------------
#define LROW 272                 // padded smem row bytes (128 bf16 -> 136)
#define LTILE (32 * LROW)        // 8704 B per matrix tile
#define LSM_STEP (2 * 4 * LTILE) // 69632 B

__global__ __launch_bounds__(256) void lstm_step_mma(
    const float* __restrict__ pre,      // [B*T,4d] (contains bih), gate-major
    const __nv_bfloat16* __restrict__ W0,  // [4d][dkp] hi, permuted rows
    const __nv_bfloat16* __restrict__ W1,  // [4d][dkp] lo, permuted rows
    const float* __restrict__ bhh,      // [4d] gate-major
    const __nv_bfloat16* __restrict__ hbf_in,  // [2][32][dkp] hi|lo
    float* __restrict__ cT,             // [d][32]
    __nv_bfloat16* __restrict__ hbf_out,
    float* __restrict__ hfin, float* __restrict__ cfin,
    float* __restrict__ y,              // [B,T,d]
    int t, int d, int dkp)
{
    extern __shared__ char dynsm[];

    const int tid  = threadIdx.x;
    const int wid  = tid >> 5;
    const int lane = tid & 31;
    const int mtx  = wid & 3;            // staged matrix: A0,A1,B0,B1
    const int half = wid >> 2;           // k-half of chunk / compute k-group
    const int n0   = blockIdx.x * 32;

    // source row for staging (row = lane)
    const __nv_bfloat16* srow;
    if      (mtx == 0) srow = hbf_in + (size_t)lane * dkp;
    else if (mtx == 1) srow = hbf_in + (size_t)(32 + lane) * dkp;
    else if (mtx == 2) srow = W0 + (size_t)(n0 + lane) * dkp;
    else               srow = W1 + (size_t)(n0 + lane) * dkp;

    const int niter = dkp >> 7;          // chunks of 128

    uint4 pf[8];
    {
        const uint4* s = (const uint4*)srow + half * 8;
        #pragma unroll
        for (int u = 0; u < 8; ++u) pf[u] = s[u];
    }

    float acc[2][4];
    #pragma unroll
    for (int mf = 0; mf < 2; ++mf)
        #pragma unroll
        for (int i = 0; i < 4; ++i) acc[mf][i] = 0.f;

    const int ntile = wid & 3;
    const int arow  = lane >> 2;
    const int browo = (ntile * 8 + arow) * LROW;

    int buf = 0;
    for (int c = 0; c < niter; ++c) {
        // store prefetched half-chunk
        {
            char* dst = dynsm + (size_t)(buf * 4 + mtx) * LTILE
                        + lane * LROW + half * 128;
            #pragma unroll
            for (int u = 0; u < 8; ++u) *(uint4*)(dst + u * 16) = pf[u];
        }
        __syncthreads();

        if (c + 1 < niter) {
            const uint4* s = (const uint4*)srow + (c + 1) * 16 + half * 8;
            #pragma unroll
            for (int u = 0; u < 8; ++u) pf[u] = s[u];
        }

        const char* a0t = dynsm + (size_t)(buf * 4 + 0) * LTILE;
        const char* a1t = dynsm + (size_t)(buf * 4 + 1) * LTILE;
        const char* b0t = dynsm + (size_t)(buf * 4 + 2) * LTILE;
        const char* b1t = dynsm + (size_t)(buf * 4 + 3) * LTILE;

        #pragma unroll
        for (int ksl = 0; ksl < 4; ++ksl) {
            const int ks = half * 4 + ksl;
            const int kb = ks * 32 + (lane & 3) * 4;

            const uint32_t b0a = *(const uint32_t*)(b0t + browo + kb);
            const uint32_t b0b = *(const uint32_t*)(b0t + browo + kb + 16);
            const uint32_t b1a = *(const uint32_t*)(b1t + browo + kb);
            const uint32_t b1b = *(const uint32_t*)(b1t + browo + kb + 16);

            #pragma unroll
            for (int mf = 0; mf < 2; ++mf) {
                const int mr = (mf * 16 + arow) * LROW;
                const uint32_t a00 = *(const uint32_t*)(a0t + mr + kb);
                const uint32_t a01 = *(const uint32_t*)(a0t + mr + 8 * LROW + kb);
                const uint32_t a02 = *(const uint32_t*)(a0t + mr + kb + 16);
                const uint32_t a03 = *(const uint32_t*)(a0t + mr + 8 * LROW + kb + 16);
                hmma16816(acc[mf][0], acc[mf][1], acc[mf][2], acc[mf][3],
                          a00, a01, a02, a03, b0a, b0b);
                hmma16816(acc[mf][0], acc[mf][1], acc[mf][2], acc[mf][3],
                          a00, a01, a02, a03, b1a, b1b);
                const uint32_t a10 = *(const uint32_t*)(a1t + mr + kb);
                const uint32_t a11 = *(const uint32_t*)(a1t + mr + 8 * LROW + kb);
                const uint32_t a12 = *(const uint32_t*)(a1t + mr + kb + 16);
                const uint32_t a13 = *(const uint32_t*)(a1t + mr + 8 * LROW + kb + 16);
                hmma16816(acc[mf][0], acc[mf][1], acc[mf][2], acc[mf][3],
                          a10, a11, a12, a13, b0a, b0b);
            }
        }
        buf ^= 1;
    }

    // combine k-groups via smem psum (overlay on tile memory)
    __syncthreads();
    float* psum = (float*)dynsm;       // [4 warps][32 lanes][8]
    if (wid >= 4) {
        float* p = psum + ((size_t)(wid - 4) * 32 + lane) * 8;
        #pragma unroll
        for (int mf = 0; mf < 2; ++mf)
            #pragma unroll
            for (int i = 0; i < 4; ++i) p[mf * 4 + i] = acc[mf][i];
    }
    __syncthreads();

    if (wid < 4) {
        const float* p = psum + ((size_t)wid * 32 + lane) * 8;
        #pragma unroll
        for (int mf = 0; mf < 2; ++mf)
            #pragma unroll
            for (int i = 0; i < 4; ++i) acc[mf][i] += p[mf * 4 + i];

        // gather partner's gates (cols +-2): pairs (0,1),(2,3) of lane&3
        float po[2][4];
        #pragma unroll
        for (int mf = 0; mf < 2; ++mf)
            #pragma unroll
            for (int i = 0; i < 4; ++i)
                po[mf][i] = __shfl_xor_sync(0xffffffffu, acc[mf][i], 1);

        if ((lane & 1) == 0) {
            const int u = (n0 + (wid & 3) * 8 + (lane & 3) * 2) >> 2;
            #pragma unroll
            for (int mf = 0; mf < 2; ++mf) {
                #pragma unroll
                for (int rr = 0; rr < 2; ++rr) {
                    const int b = mf * 16 + (lane >> 2) + rr * 8;
                    const float* pp = pre + (size_t)(b * Tt + t) * (4 * d);
                    const float gi = acc[mf][rr * 2 + 0] + pp[            u] + bhh[            u];
                    const float gf = acc[mf][rr * 2 + 1] + pp[    d + u] + bhh[    d + u];
                    const float gg = po [mf][rr * 2 + 0] + pp[2 * d + u] + bhh[2 * d + u];
                    const float go = po [mf][rr * 2 + 1] + pp[3 * d + u] + bhh[3 * d + u];

                    const float si = 1.f / (1.f + expf(-gi));
                    const float sf = 1.f / (1.f + expf(-gf));
                    const float so = 1.f / (1.f + expf(-go));
                    const float cn = sf * cT[u * 32 + b] + si * tanhf(gg);
                    const float hn = so * tanhf(cn);

                    cT[u * 32 + b] = cn;
                    y[(size_t)(b * Tt + t) * d + u] = hn;
                    const __nv_bfloat16 hhi = __float2bfloat16(hn);
                    hbf_out[(size_t)b * dkp + u] = hhi;
                    hbf_out[(size_t)(32 + b) * dkp + u] =
                        __float2bfloat16(hn - __bfloat162float(hhi));
                    if (t == Tt - 1) {
                        hfin[(size_t)b * d + u] = hn;
                        cfin[(size_t)b * d + u] = cn;
                    }
                }
            }
        }
    }
}

// ---------------------------------------------------------------------------
// Logits GEMM on legacy tensor cores (unchanged from passing round 12)
// ---------------------------------------------------------------------------
#define LDP 40
#define LG_TILE (128 * LDP * 2)
#define LG_SMEM (4 * LG_TILE)

__global__ __launch_bounds__(256, 2) void logits_hmma(
    const __nv_bfloat16* __restrict__ A0, const __nv_bfloat16* __restrict__ A1,
    const __nv_bfloat16* __restrict__ B0, const __nv_bfloat16* __restrict__ B1,
    float* __restrict__ out)
{
    extern __shared__ char smc[];

    const int tid  = threadIdx.x;
    const int wid  = tid >> 5;
    const int lane = tid & 31;
    const int wm   = wid & 1;
    const int wn   = wid >> 1;

    const int n0 = blockIdx.x * 128;
    const int m0 = blockIdx.y * 128;

    const int mtx = tid >> 6;
    const int rp  = tid & 63;
    const __nv_bfloat16* srcbase =
        (mtx == 0) ? A0 + (size_t)(m0 + 2 * rp) * LK :
        (mtx == 1) ? A1 + (size_t)(m0 + 2 * rp) * LK :
        (mtx == 2) ? B0 + (size_t)(n0 + 2 * rp) * LK :
                     B1 + (size_t)(n0 + 2 * rp) * LK;
    char* dst0 = smc + mtx * LG_TILE + (2 * rp    ) * (LDP * 2);
    char* dst1 = smc + mtx * LG_TILE + (2 * rp + 1) * (LDP * 2);

    float acc[4][4][4];
    #pragma unroll
    for (int i = 0; i < 4; ++i)
        #pragma unroll
        for (int j = 0; j < 4; ++j)
            #pragma unroll
            for (int k = 0; k < 4; ++k) acc[i][j][k] = 0.f;

    const char* asm0 = smc;
    const char* asm1 = smc + LG_TILE;
    const char* bsm0 = smc + 2 * LG_TILE;
    const char* bsm1 = smc + 3 * LG_TILE;

    const int arow = (lane >> 2);
    const int akof = (lane & 3) * 2;

    for (int c = 0; c < LK / 32; ++c) {
        __syncthreads();
        {
            const char* s0 = (const char*)(srcbase + c * 32);
            const char* s1 = (const char*)(srcbase + LK + c * 32);
            #pragma unroll
            for (int i = 0; i < 4; ++i) {
                *(uint4*)(dst0 + i * 16) = *(const uint4*)(s0 + i * 16);
                *(uint4*)(dst1 + i * 16) = *(const uint4*)(s1 + i * 16);
            }
        }
        __syncthreads();

        #pragma unroll
        for (int ks = 0; ks < 2; ++ks) {
            const int kbyte = (ks * 16 + akof) * 2;

            uint32_t b0f[4][2], b1f[4][2];
            #pragma unroll
            for (int nf = 0; nf < 4; ++nf) {
                const int nr = (wn * 32 + nf * 8 + arow) * (LDP * 2);
                b0f[nf][0] = *(const uint32_t*)(bsm0 + nr + kbyte);
                b0f[nf][1] = *(const uint32_t*)(bsm0 + nr + kbyte + 16);
                b1f[nf][0] = *(const uint32_t*)(bsm1 + nr + kbyte);
                b1f[nf][1] = *(const uint32_t*)(bsm1 + nr + kbyte + 16);
            }

            uint32_t af[4][4];
            #pragma unroll
            for (int mf = 0; mf < 4; ++mf) {
                const int mr = (wm * 64 + mf * 16 + arow) * (LDP * 2);
                af[mf][0] = *(const uint32_t*)(asm0 + mr + kbyte);
                af[mf][1] = *(const uint32_t*)(asm0 + mr + 8 * (LDP * 2) + kbyte);
                af[mf][2] = *(const uint32_t*)(asm0 + mr + kbyte + 16);
                af[mf][3] = *(const uint32_t*)(asm0 + mr + 8 * (LDP * 2) + kbyte + 16);
            }
            #pragma unroll
            for (int mf = 0; mf < 4; ++mf)
                #pragma unroll
                for (int nf = 0; nf < 4; ++nf) {
                    hmma16816(acc[mf][nf][0], acc[mf][nf][1], acc[mf][nf][2], acc[mf][nf][3],
                              af[mf][0], af[mf][1], af[mf][2], af[mf][3],
                              b0f[nf][0], b0f[nf][1]);
                    hmma16816(acc[mf][nf][0], acc[mf][nf][1], acc[mf][nf][2], acc[mf][nf][3],
                              af[mf][0], af[mf][1], af[mf][2], af[mf][3],
                              b1f[nf][0], b1f[nf][1]);
                }

            #pragma unroll
            for (int mf = 0; mf < 4; ++mf) {
                const int mr = (wm * 64 + mf * 16 + arow) * (LDP * 2);
                af[mf][0] = *(const uint32_t*)(asm1 + mr + kbyte);
                af[mf][1] = *(const uint32_t*)(asm1 + mr + 8 * (LDP * 2) + kbyte);
                af[mf][2] = *(const uint32_t*)(asm1 + mr + kbyte + 16);
                af[mf][3] = *(const uint32_t*)(asm1 + mr + 8 * (LDP * 2) + kbyte + 16);
            }
            #pragma unroll
            for (int mf = 0; mf < 4; ++mf)
                #pragma unroll
                for (int nf = 0; nf < 4; ++nf)
                    hmma16816(acc[mf][nf][0], acc[mf][nf][1], acc[mf][nf][2], acc[mf][nf][3],
                              af[mf][0], af[mf][1], af[mf][2], af[mf][3],
                              b0f[nf][0], b0f[nf][1]);
        }
    }

    #pragma unroll
    for (int mf = 0; mf < 4; ++mf) {
        const int mrow = m0 + wm * 64 + mf * 16 + arow;
        #pragma unroll
        for (int nf = 0; nf < 4; ++nf) {
            const int ncol = n0 + wn * 32 + nf * 8 + (lane & 3) * 2;
            *(float2*)(out + (size_t)mrow * Vv + ncol) =
                make_float2(acc[mf][nf][0], acc[mf][nf][1]);
            *(float2*)(out + (size_t)(mrow + 8) * Vv + ncol) =
                make_float2(acc[mf][nf][2], acc[mf][nf][3]);
        }
    }
}

// ---- helpers ----
// split Whh (fp32, gate-major [4d][d]) -> permuted bf16 hi/lo [4d][dkp]
// with row nn = unit*4 + gate, K zero-padded to dkp.
__device__ __forceinline__ void whh_split_body(
    size_t idx, const float* W, __nv_bfloat16* W0, __nv_bfloat16* W1,
    int d, int dkp)
{
    const int k  = (int)(idx % dkp);
    const int nn = (int)(idx / dkp);
    const int jj = nn >> 2, g = nn & 3;
    const float v = (k < d) ? W[((size_t)g * d + jj) * d + k] : 0.f;
    const __nv_bfloat16 hi = __float2bfloat16(v);
    W0[idx] = hi;
    W1[idx] = __float2bfloat16(v - __bfloat162float(hi));
}

__global__ void split_whh(const float* __restrict__ W,
                          __nv_bfloat16* __restrict__ W0,
                          __nv_bfloat16* __restrict__ W1, int d, int dkp)
{
    size_t idx = (size_t)blockIdx.x * 256 + threadIdx.x;
    if (idx < (size_t)4 * d * dkp) whh_split_body(idx, W, W0, W1, d, dkp);
}

// fused prep: WT transpose + layer-0 state init + Whh0 split
__global__ void prep_all(const float* __restrict__ dW, float* __restrict__ WT,
                         const float* __restrict__ h0, const float* __restrict__ c0,
                         __nv_bfloat16* __restrict__ hbf, float* __restrict__ cT,
                         const float* __restrict__ Whh0,
                         __nv_bfloat16* __restrict__ W0, __nv_bfloat16* __restrict__ W1)
{
    size_t idx = (size_t)blockIdx.x * 256 + threadIdx.x;
    if (idx < (size_t)Mm * Ee) {
        int n = (int)(idx / Ee), k = (int)(idx % Ee);
        WT[idx] = dW[(size_t)k * Mm + n];
    }
    if (idx < (size_t)32 * Hh) {
        int b = (int)(idx / Hh), u = (int)(idx % Hh);
        float hv = h0[(size_t)b * Hh + u];
        __nv_bfloat16 hi = __float2bfloat16(hv);
        hbf[idx] = hi;
        hbf[(size_t)32 * Hh + idx] = __float2bfloat16(hv - __bfloat162float(hi));
        cT[u * 32 + b] = c0[(size_t)b * Hh + u];
    }
    if (idx < (size_t)4 * Hh * Hh) whh_split_body(idx, Whh0, W0, W1, Hh, Hh);
}

__global__ void state_init(const float* __restrict__ h0, const float* __restrict__ c0,
                           __nv_bfloat16* __restrict__ hbf, float* __restrict__ cT,
                           int d, int dkp)
{
    int idx = blockIdx.x * 256 + threadIdx.x;
    if (idx < 32 * dkp) {
        int b = idx / dkp, u = idx % dkp;
        float hv = (u < d) ? h0[(size_t)b * d + u] : 0.f;
        __nv_bfloat16 hi = __float2bfloat16(hv);
        hbf[idx] = hi;
        hbf[32 * dkp + idx] = __float2bfloat16(hv - __bfloat162float(hi));
        if (u < d) cT[u * 32 + b] = c0[(size_t)b * d + u];
    }
}

// fp32 [R][K0] -> hi/lo bf16 [R][LK] with zero K-padding (logits operands)
__global__ void split_bf16(const float* __restrict__ src,
                           __nv_bfloat16* __restrict__ d0,
                           __nv_bfloat16* __restrict__ d1, int R, int K0)
{
    size_t idx = (size_t)blockIdx.x * 256 + threadIdx.x;
    if (idx < (size_t)R * LK) {
        int k = (int)(idx % LK);
        int rr = (int)(idx / LK);
        float v = (k < K0) ? src[(size_t)rr * K0 + k] : 0.f;
        __nv_bfloat16 hi = __float2bfloat16(v);
        d0[idx] = hi;
        d1[idx] = __float2bfloat16(v - __bfloat162float(hi));
    }
}

// ---------------------------------------------------------------------------
extern "C" void kernel_launch(void* const* d_in, const int* in_sizes, int n_in,
                              void* d_out, int out_size)
{
    (void)in_sizes; (void)n_in; (void)out_size;

    const int*   ids  = (const int*)  d_in[0];
    const float* emb  = (const float*)d_in[1];
    const float* dW   = (const float*)d_in[2];
    const float* db   = (const float*)d_in[3];
    const float* Wih0 = (const float*)d_in[4];
    const float* Whh0 = (const float*)d_in[5];
    const float* bih0 = (const float*)d_in[6];
    const float* bhh0 = (const float*)d_in[7];
    const float* h00  = (const float*)d_in[8];
    const float* c00  = (const float*)d_in[9];
    const float* Wih1 = (const float*)d_in[10];
    const float* Whh1 = (const float*)d_in[11];
    const float* bih1 = (const float*)d_in[12];
    const float* bhh1 = (const float*)d_in[13];
    const float* h01  = (const float*)d_in[14];
    const float* c01  = (const float*)d_in[15];
    const float* Wih2 = (const float*)d_in[16];
    const float* Whh2 = (const float*)d_in[17];
    const float* bih2 = (const float*)d_in[18];
    const float* bhh2 = (const float*)d_in[19];
    const float* h02  = (const float*)d_in[20];
    const float* c02  = (const float*)d_in[21];
    float* out = (float*)d_out;

    float *PRE, *X0, *Y0, *Y1, *Y2, *WT, *CT;
    __nv_bfloat16 *HB, *WS0, *WS1, *E0, *E1, *A0s, *A1s;
    cudaGetSymbolAddress((void**)&PRE, g_PRE);
    cudaGetSymbolAddress((void**)&X0,  g_X0);
    cudaGetSymbolAddress((void**)&Y0,  g_Y0);
    cudaGetSymbolAddress((void**)&Y1,  g_Y1);
    cudaGetSymbolAddress((void**)&Y2,  g_Y2);
    cudaGetSymbolAddress((void**)&WT,  g_WT);
    cudaGetSymbolAddress((void**)&CT,  g_CT);
    cudaGetSymbolAddress((void**)&HB,  g_HB);
    cudaGetSymbolAddress((void**)&WS0, g_WS0);
    cudaGetSymbolAddress((void**)&WS1, g_WS1);
    cudaGetSymbolAddress((void**)&E0,  g_E0);
    cudaGetSymbolAddress((void**)&E1,  g_E1);
    cudaGetSymbolAddress((void**)&A0s, g_A0);
    cudaGetSymbolAddress((void**)&A1s, g_A1);
    __nv_bfloat16* HBp[2] = { HB, HB + 2 * 32 * Hh };

    cudaFuncSetAttribute(lstm_step_mma,
                         cudaFuncAttributeMaxDynamicSharedMemorySize, LSM_STEP);
    cudaFuncSetAttribute(logits_hmma,
                         cudaFuncAttributeMaxDynamicSharedMemorySize, LG_SMEM);

    const size_t OFF_H0 = (size_t)Bb * Tt * Vv;
    const size_t OFF_C0 = OFF_H0 + (size_t)Bb * Hh;
    const size_t OFF_H1 = OFF_C0 + (size_t)Bb * Hh;
    const size_t OFF_C1 = OFF_H1 + (size_t)Bb * Hh;
    const size_t OFF_H2 = OFF_C1 + (size_t)Bb * Hh;
    const size_t OFF_C2 = OFF_H2 + (size_t)Bb * Ee;

    // #1 prep (WT + state0 + Whh0 split), #2 DeFINE, #3 layer-0 GEMM,
    // #4 lstm_step_mma t=0  <- ncu sample target
    prep_all<<<(int)(((size_t)4 * Hh * Hh + 255) / 256), 256>>>(
        dW, WT, h00, c00, HBp[0], CT, Whh0, WS0, WS1);
    gemm_nt<<<dim3(Mm / GBN, NT / GBM), 256>>>(emb, WT, X0, db, ids,
                                               NT, Mm, Ee);
    gemm_nt<<<dim3(4 * Hh / GBN, NT / GBM), 256>>>(X0, Wih0, PRE, bih0,
                                                   nullptr, NT, 4 * Hh, Mm);

    // ================= layer 0 recurrence =================
    for (int t = 0; t < Tt; ++t) {
        int s = t & 1;
        lstm_step_mma<<<4 * Hh / 32, 256, LSM_STEP>>>(
            PRE, WS0, WS1, bhh0, HBp[s], CT, HBp[1 - s],
            out + OFF_H0, out + OFF_C0, Y0, t, Hh, Hh);
    }

    // ================= layer 1 =================
    gemm_nt<<<dim3(4 * Hh / GBN, NT / GBM), 256>>>(Y0, Wih1, PRE, bih1, nullptr,
                                                   NT, 4 * Hh, Hh);
    split_whh<<<(int)(((size_t)4 * Hh * Hh + 255) / 256), 256>>>(
        Whh1, WS0, WS1, Hh, Hh);
    state_init<<<(32 * Hh + 255) / 256, 256>>>(h01, c01, HBp[0], CT, Hh, Hh);
    for (int t = 0; t < Tt; ++t) {
        int s = t & 1;
        lstm_step_mma<<<4 * Hh / 32, 256, LSM_STEP>>>(
            PRE, WS0, WS1, bhh1, HBp[s], CT, HBp[1 - s],
            out + OFF_H1, out + OFF_C1, Y1, t, Hh, Hh);
    }

    // ================= layer 2 =================
    gemm_nt<<<dim3((4 * Ee + GBN - 1) / GBN, NT / GBM), 256>>>(
        Y1, Wih2, PRE, bih2, nullptr, NT, 4 * Ee, Hh);
    split_whh<<<(int)(((size_t)4 * Ee * DKE + 255) / 256), 256>>>(
        Whh2, WS0, WS1, Ee, DKE);
    state_init<<<(32 * DKE + 255) / 256, 256>>>(h02, c02, HBp[0], CT, Ee, DKE);
    for (int t = 0; t < Tt; ++t) {
        int s = t & 1;
        lstm_step_mma<<<4 * Ee / 32, 256, LSM_STEP>>>(
            PRE, WS0, WS1, bhh2, HBp[s], CT, HBp[1 - s],
            out + OFF_H2, out + OFF_C2, Y2, t, Ee, DKE);
    }

    // ---- tied-embedding logits on tensor cores ----
    split_bf16<<<(int)(((size_t)Vv * LK + 255) / 256), 256>>>(emb, E0, E1, Vv, Ee);
    split_bf16<<<(int)(((size_t)NT * LK + 255) / 256), 256>>>(Y2, A0s, A1s, NT, Ee);
    logits_hmma<<<dim3(Vv / 128, NT / 128), 256, LG_SMEM>>>(A0s, A1s, E0, E1, out);
}